// round 3
// baseline (speedup 1.0000x reference)
#include <cuda_runtime.h>
#include <cuda_bf16.h>

#define T_DIM 64
#define B_DIM 16
#define S_DIM 256
#define D_DIM 512
#define T_TILE 4       // t-rows per logits block
#define T_AV   16      // t-rows per AV block

// scratch: h = input @ W_comb + b_comb, stored (B, T, D)
__device__ float g_h[B_DIM * T_DIM * D_DIM];

__device__ __forceinline__ float tanh_ap(float x) {
    float y;
    asm("tanh.approx.f32 %0, %1;" : "=f"(y) : "f"(x));
    return y;
}

// ---------------------------------------------------------------------------
// Kernel 1: h[b,t,:] = input[t,b,:] @ W + bias   (M=1024, N=512, K=512)
// ---------------------------------------------------------------------------
__global__ __launch_bounds__(256) void gemm_kernel(
    const float* __restrict__ A,
    const float* __restrict__ W,
    const float* __restrict__ bias)
{
    __shared__ float As[64][33];
    __shared__ float Bs[32][68];

    const int tid = threadIdx.x;
    const int tx = tid & 15;
    const int ty = tid >> 4;
    const int m0 = blockIdx.y * 64;
    const int n0 = blockIdx.x * 64;

    float acc[4][4];
#pragma unroll
    for (int i = 0; i < 4; ++i)
#pragma unroll
        for (int j = 0; j < 4; ++j) acc[i][j] = 0.f;

    for (int k0 = 0; k0 < D_DIM; k0 += 32) {
#pragma unroll
        for (int i = tid; i < 64 * 32; i += 256) {
            int r = i >> 5, c = i & 31;
            As[r][c] = A[(size_t)(m0 + r) * D_DIM + k0 + c];
        }
#pragma unroll
        for (int i = tid; i < 32 * 64; i += 256) {
            int r = i >> 6, c = i & 63;
            Bs[r][c] = W[(size_t)(k0 + r) * D_DIM + n0 + c];
        }
        __syncthreads();

#pragma unroll
        for (int k = 0; k < 32; ++k) {
            float4 b4 = *(const float4*)&Bs[k][tx * 4];
            float a0 = As[ty * 4 + 0][k];
            float a1 = As[ty * 4 + 1][k];
            float a2 = As[ty * 4 + 2][k];
            float a3 = As[ty * 4 + 3][k];
            acc[0][0] += a0 * b4.x; acc[0][1] += a0 * b4.y; acc[0][2] += a0 * b4.z; acc[0][3] += a0 * b4.w;
            acc[1][0] += a1 * b4.x; acc[1][1] += a1 * b4.y; acc[1][2] += a1 * b4.z; acc[1][3] += a1 * b4.w;
            acc[2][0] += a2 * b4.x; acc[2][1] += a2 * b4.y; acc[2][2] += a2 * b4.z; acc[2][3] += a2 * b4.w;
            acc[3][0] += a3 * b4.x; acc[3][1] += a3 * b4.y; acc[3][2] += a3 * b4.z; acc[3][3] += a3 * b4.w;
        }
        __syncthreads();
    }

#pragma unroll
    for (int i = 0; i < 4; ++i) {
        int m = m0 + ty * 4 + i;
        int bb = m & (B_DIM - 1);
        int tt = m >> 4;
        float* dst = &g_h[((size_t)bb * T_DIM + tt) * D_DIM + n0 + tx * 4];
#pragma unroll
        for (int j = 0; j < 4; ++j)
            dst[j] = acc[i][j] + bias[n0 + tx * 4 + j];
    }
}

// ---------------------------------------------------------------------------
// Kernel 2: logits + softmax. grid=(B, T/4)=256 blocks, 512 thr, <=64 regs.
// Warp w: quarter q=w&3 (128-dim slice of D), sg=w>>2 (64 s values).
// Each lane holds 1 float4 of h per t (si-invariant), context prefetch depth 2.
// Softmax (warps 0..3) sums 4 quarter-partials, writes probs to out_attn.
// ---------------------------------------------------------------------------
__global__ __launch_bounds__(512, 2) void logits_kernel(
    const float* __restrict__ context,   // (B,S,D)
    const float* __restrict__ v_w,       // (D)
    const float* __restrict__ v_b,       // scalar
    float* __restrict__ out_attn)        // (B*T, S) -> normalized probs
{
    __shared__ float h_s[T_TILE * D_DIM];          // 8 KB
    __shared__ float lg[4][T_TILE][S_DIM];         // 16 KB (quarter-partials)

    const int b    = blockIdx.x;
    const int t0   = blockIdx.y * T_TILE;
    const int tid  = threadIdx.x;
    const int wid  = tid >> 5;
    const int lane = tid & 31;
    const int q    = wid & 3;          // D quarter
    const int sg   = wid >> 2;         // s group (64 s each)

    {
        const float4* hp = (const float4*)(g_h + ((size_t)b * T_DIM + t0) * D_DIM);
        float4* hs4 = (float4*)h_s;
        for (int i = tid; i < T_TILE * D_DIM / 4; i += 512) hs4[i] = hp[i];
    }
    __syncthreads();

    // ---- logits ----
    {
        const int dof = q * 32 + lane;                  // float4 idx within row (0..127)
        const float4* h4 = (const float4*)h_s;
        float4 hh[T_TILE];
#pragma unroll
        for (int t = 0; t < T_TILE; ++t)
            hh[t] = h4[t * (D_DIM / 4) + dof];
        const float4 ww = ((const float4*)v_w)[dof];

        const float4* cbase = (const float4*)(context + (size_t)b * S_DIM * D_DIM)
                              + (size_t)(sg * 64) * (D_DIM / 4) + dof;

        float4 c0 = cbase[0];
        float4 c1 = cbase[1 * (D_DIM / 4)];

        for (int si = 0; si < 64; ++si) {
            int pf = si + 2 < 64 ? si + 2 : 63;
            float4 cn = cbase[(size_t)pf * (D_DIM / 4)];

            float acc[T_TILE];
#pragma unroll
            for (int t = 0; t < T_TILE; ++t) {
                float a;
                a  = ww.x * tanh_ap(hh[t].x + c0.x);
                a += ww.y * tanh_ap(hh[t].y + c0.y);
                a += ww.z * tanh_ap(hh[t].z + c0.z);
                a += ww.w * tanh_ap(hh[t].w + c0.w);
                acc[t] = a;
            }
#pragma unroll
            for (int t = 0; t < T_TILE; ++t) {
                float v = acc[t];
                v += __shfl_xor_sync(0xffffffffu, v, 16);
                v += __shfl_xor_sync(0xffffffffu, v, 8);
                v += __shfl_xor_sync(0xffffffffu, v, 4);
                v += __shfl_xor_sync(0xffffffffu, v, 2);
                v += __shfl_xor_sync(0xffffffffu, v, 1);
                if (lane == 0) lg[q][t][sg * 64 + si] = v;
            }
            c0 = c1; c1 = cn;
        }
    }
    __syncthreads();

    // ---- softmax: warps 0..3, row t = wid ----
    if (wid < T_TILE) {
        const float vb = v_b[0];
        const int t = wid;
        float e[8];
        float m = -1e30f;
#pragma unroll
        for (int k = 0; k < 8; ++k) {
            int i = k * 32 + lane;
            e[k] = lg[0][t][i] + lg[1][t][i] + lg[2][t][i] + lg[3][t][i] + vb;
            m = fmaxf(m, e[k]);
        }
#pragma unroll
        for (int o = 16; o; o >>= 1) m = fmaxf(m, __shfl_xor_sync(0xffffffffu, m, o));
        float ssum = 0.f;
#pragma unroll
        for (int k = 0; k < 8; ++k) {
            e[k] = __expf(e[k] - m);
            ssum += e[k];
        }
#pragma unroll
        for (int o = 16; o; o >>= 1) ssum += __shfl_xor_sync(0xffffffffu, ssum, o);
        const float inv = 1.0f / ssum;
        float* oa = out_attn + ((size_t)b * T_DIM + t0 + t) * S_DIM;
#pragma unroll
        for (int k = 0; k < 8; ++k)
            oa[k * 32 + lane] = e[k] * inv;
    }
}

// ---------------------------------------------------------------------------
// Kernel 3: weighted = attn @ values. grid=(B, 2, T/16)=128 blocks, 256 thr.
// Block owns 16 t-rows and a 256-wide d-half. Probs staged in SMEM.
// ---------------------------------------------------------------------------
__global__ __launch_bounds__(256) void av_kernel(
    const float* __restrict__ values,    // (B,S,D)
    const float* __restrict__ attn,      // (B*T, S) normalized
    float* __restrict__ out_w)           // (T,B,D)
{
    __shared__ float p_s[T_AV][S_DIM];   // 16 KB

    const int b   = blockIdx.x;
    const int dh  = blockIdx.y;          // d half
    const int t0  = blockIdx.z * T_AV;
    const int tid = threadIdx.x;

    {
        const float4* ap = (const float4*)(attn + ((size_t)b * T_DIM + t0) * S_DIM);
        float4* ps4 = (float4*)p_s;
        for (int i = tid; i < T_AV * S_DIM / 4; i += 256) ps4[i] = ap[i];
    }
    __syncthreads();

    const int d = dh * 256 + tid;
    const float* vp = values + (size_t)b * S_DIM * D_DIM + d;

    float w[T_AV];
#pragma unroll
    for (int t = 0; t < T_AV; ++t) w[t] = 0.f;

    float v0 = vp[0 * D_DIM];
    float v1 = vp[1 * D_DIM];
    float v2 = vp[2 * D_DIM];
    float v3 = vp[3 * D_DIM];

    for (int s = 0; s < S_DIM; s += 4) {
        float n0, n1, n2, n3;
        if (s + 4 < S_DIM) {
            n0 = vp[(size_t)(s + 4) * D_DIM];
            n1 = vp[(size_t)(s + 5) * D_DIM];
            n2 = vp[(size_t)(s + 6) * D_DIM];
            n3 = vp[(size_t)(s + 7) * D_DIM];
        }
#pragma unroll
        for (int t = 0; t < T_AV; ++t) {
            float4 p = *(const float4*)&p_s[t][s];
            w[t] += p.x * v0 + p.y * v1 + p.z * v2 + p.w * v3;
        }
        v0 = n0; v1 = n1; v2 = n2; v3 = n3;
    }

#pragma unroll
    for (int t = 0; t < T_AV; ++t)
        out_w[((size_t)(t0 + t) * B_DIM + b) * D_DIM + d] = w[t];
}

// ---------------------------------------------------------------------------
extern "C" void kernel_launch(void* const* d_in, const int* in_sizes, int n_in,
                              void* d_out, int out_size) {
    const float* input   = (const float*)d_in[0];
    const float* context = (const float*)d_in[1];
    const float* values  = (const float*)d_in[2];
    const float* W_comb  = (const float*)d_in[3];
    const float* b_comb  = (const float*)d_in[4];
    const float* v_w     = (const float*)d_in[5];
    const float* v_b     = (const float*)d_in[6];

    float* out_weighted = (float*)d_out;                                 // (T,B,D)
    float* out_attn     = (float*)d_out + (size_t)T_DIM * B_DIM * D_DIM; // (B*T,S)

    dim3 g1(D_DIM / 64, (T_DIM * B_DIM) / 64);           // (8,16)
    gemm_kernel<<<g1, 256>>>(input, W_comb, b_comb);

    dim3 g2(B_DIM, T_DIM / T_TILE);                      // (16,16) = 256 blocks
    logits_kernel<<<g2, 512>>>(context, v_w, v_b, out_attn);

    dim3 g3(B_DIM, 2, T_DIM / T_AV);                     // (16,2,4) = 128 blocks
    av_kernel<<<g3, 256>>>(values, out_attn, out_weighted);
}

// round 5
// speedup vs baseline: 1.0912x; 1.0912x over previous
#include <cuda_runtime.h>
#include <cuda_bf16.h>

#define T_DIM 64
#define B_DIM 16
#define S_DIM 256
#define D_DIM 512
#define T_TILE 4       // t-rows per logits block
#define T_AV   16      // t-rows per AV block

// scratch: h = input @ W_comb + b_comb, stored (B, T, D)
__device__ float g_h[B_DIM * T_DIM * D_DIM];

__device__ __forceinline__ float tanh_ap(float x) {
    float y;
    asm("tanh.approx.f32 %0, %1;" : "=f"(y) : "f"(x));
    return y;
}

// ---------------------------------------------------------------------------
// Kernel 1: h[b,t,:] = input[t,b,:] @ W + bias   (M=1024, N=512, K=512)
// 64x64 tile, 256 thr, 4x4 microtile, double-buffered SMEM, 2 CTAs/SM.
// As rows padded to 33 floats (conflict-free scalar column reads) -> scalar STS.
// Bs rows padded to 68 floats (272B, 16B-aligned) -> float4 STS/LDS.
// ---------------------------------------------------------------------------
__global__ __launch_bounds__(256, 2) void gemm_kernel(
    const float* __restrict__ A,
    const float* __restrict__ W,
    const float* __restrict__ bias)
{
    __shared__ float As[2][64][33];
    __shared__ float Bs[2][32][68];

    const int tid = threadIdx.x;
    const int tx = tid & 15;
    const int ty = tid >> 4;
    const int m0 = blockIdx.y * 64;
    const int n0 = blockIdx.x * 64;

    // A tile: 64x32 floats = 512 float4; thread loads f4 idx {tid, tid+256}
    const int ar0 = tid >> 3,         ac0 = (tid & 7) * 4;
    const int ar1 = (tid + 256) >> 3, ac1 = ((tid + 256) & 7) * 4;
    // B tile: 32x64 floats = 512 float4; thread loads f4 idx {tid, tid+256}
    const int br0 = tid >> 4,         bc0 = (tid & 15) * 4;
    const int br1 = (tid + 256) >> 4, bc1 = ((tid + 256) & 15) * 4;

    float acc[4][4];
#pragma unroll
    for (int i = 0; i < 4; ++i)
#pragma unroll
        for (int j = 0; j < 4; ++j) acc[i][j] = 0.f;

    // prologue: k0 = 0 tile -> buffer 0
    {
        float4 a0 = *(const float4*)&A[(size_t)(m0 + ar0) * D_DIM + ac0];
        float4 a1 = *(const float4*)&A[(size_t)(m0 + ar1) * D_DIM + ac1];
        float4 b0 = *(const float4*)&W[(size_t)br0 * D_DIM + n0 + bc0];
        float4 b1 = *(const float4*)&W[(size_t)br1 * D_DIM + n0 + bc1];
        As[0][ar0][ac0 + 0] = a0.x; As[0][ar0][ac0 + 1] = a0.y;
        As[0][ar0][ac0 + 2] = a0.z; As[0][ar0][ac0 + 3] = a0.w;
        As[0][ar1][ac1 + 0] = a1.x; As[0][ar1][ac1 + 1] = a1.y;
        As[0][ar1][ac1 + 2] = a1.z; As[0][ar1][ac1 + 3] = a1.w;
        *(float4*)&Bs[0][br0][bc0] = b0;
        *(float4*)&Bs[0][br1][bc1] = b1;
    }
    __syncthreads();

    int buf = 0;
    for (int k0 = 0; k0 < D_DIM; k0 += 32) {
        const bool has_next = (k0 + 32) < D_DIM;
        float4 a0, a1, b0, b1;
        if (has_next) {
            const int kn = k0 + 32;
            a0 = *(const float4*)&A[(size_t)(m0 + ar0) * D_DIM + kn + ac0];
            a1 = *(const float4*)&A[(size_t)(m0 + ar1) * D_DIM + kn + ac1];
            b0 = *(const float4*)&W[(size_t)(kn + br0) * D_DIM + n0 + bc0];
            b1 = *(const float4*)&W[(size_t)(kn + br1) * D_DIM + n0 + bc1];
        }

#pragma unroll
        for (int k = 0; k < 32; ++k) {
            float4 b4 = *(const float4*)&Bs[buf][k][tx * 4];
            float x0 = As[buf][ty * 4 + 0][k];
            float x1 = As[buf][ty * 4 + 1][k];
            float x2 = As[buf][ty * 4 + 2][k];
            float x3 = As[buf][ty * 4 + 3][k];
            acc[0][0] += x0 * b4.x; acc[0][1] += x0 * b4.y; acc[0][2] += x0 * b4.z; acc[0][3] += x0 * b4.w;
            acc[1][0] += x1 * b4.x; acc[1][1] += x1 * b4.y; acc[1][2] += x1 * b4.z; acc[1][3] += x1 * b4.w;
            acc[2][0] += x2 * b4.x; acc[2][1] += x2 * b4.y; acc[2][2] += x2 * b4.z; acc[2][3] += x2 * b4.w;
            acc[3][0] += x3 * b4.x; acc[3][1] += x3 * b4.y; acc[3][2] += x3 * b4.z; acc[3][3] += x3 * b4.w;
        }

        if (has_next) {
            const int nb = buf ^ 1;
            As[nb][ar0][ac0 + 0] = a0.x; As[nb][ar0][ac0 + 1] = a0.y;
            As[nb][ar0][ac0 + 2] = a0.z; As[nb][ar0][ac0 + 3] = a0.w;
            As[nb][ar1][ac1 + 0] = a1.x; As[nb][ar1][ac1 + 1] = a1.y;
            As[nb][ar1][ac1 + 2] = a1.z; As[nb][ar1][ac1 + 3] = a1.w;
            *(float4*)&Bs[nb][br0][bc0] = b0;
            *(float4*)&Bs[nb][br1][bc1] = b1;
        }
        __syncthreads();
        buf ^= 1;
    }

#pragma unroll
    for (int i = 0; i < 4; ++i) {
        int m = m0 + ty * 4 + i;
        int bb = m & (B_DIM - 1);
        int tt = m >> 4;
        float* dst = &g_h[((size_t)bb * T_DIM + tt) * D_DIM + n0 + tx * 4];
#pragma unroll
        for (int j = 0; j < 4; ++j)
            dst[j] = acc[i][j] + bias[n0 + tx * 4 + j];
    }
}

// ---------------------------------------------------------------------------
// Kernel 2: logits + softmax. grid=(B, T/4)=256 blocks, 512 thr, 2 CTA/SM.
// Warp w: quarter q=w&3 (128-dim slice of D), sg=w>>2 (64 s values).
// Merged-butterfly reduction: 9 shfl for all 4 accumulators.
// ---------------------------------------------------------------------------
__global__ __launch_bounds__(512, 2) void logits_kernel(
    const float* __restrict__ context,   // (B,S,D)
    const float* __restrict__ v_w,       // (D)
    const float* __restrict__ v_b,       // scalar
    float* __restrict__ out_attn)        // (B*T, S) -> normalized probs
{
    __shared__ float h_s[T_TILE * D_DIM];          // 8 KB
    __shared__ float lg[4][T_TILE][S_DIM];         // 16 KB (quarter-partials)

    const int b    = blockIdx.x;
    const int t0   = blockIdx.y * T_TILE;
    const int tid  = threadIdx.x;
    const int wid  = tid >> 5;
    const int lane = tid & 31;
    const int q    = wid & 3;
    const int sg   = wid >> 2;

    {
        const float4* hp = (const float4*)(g_h + ((size_t)b * T_DIM + t0) * D_DIM);
        float4* hs4 = (float4*)h_s;
        for (int i = tid; i < T_TILE * D_DIM / 4; i += 512) hs4[i] = hp[i];
    }
    __syncthreads();

    // ---- logits ----
    {
        const int dof = q * 32 + lane;
        const float4* h4 = (const float4*)h_s;
        float4 hh[T_TILE];
#pragma unroll
        for (int t = 0; t < T_TILE; ++t)
            hh[t] = h4[t * (D_DIM / 4) + dof];
        const float4 ww = ((const float4*)v_w)[dof];

        const float4* cbase = (const float4*)(context + (size_t)b * S_DIM * D_DIM)
                              + (size_t)(sg * 64) * (D_DIM / 4) + dof;

        float4 c0 = cbase[0];
        float4 c1 = cbase[1 * (D_DIM / 4)];

        for (int si = 0; si < 64; ++si) {
            int pf = si + 2 < 64 ? si + 2 : 63;
            float4 cn = cbase[(size_t)pf * (D_DIM / 4)];

            float acc[T_TILE];
#pragma unroll
            for (int t = 0; t < T_TILE; ++t) {
                float a;
                a  = ww.x * tanh_ap(hh[t].x + c0.x);
                a += ww.y * tanh_ap(hh[t].y + c0.y);
                a += ww.z * tanh_ap(hh[t].z + c0.z);
                a += ww.w * tanh_ap(hh[t].w + c0.w);
                acc[t] = a;
            }
            // merged butterfly: 9 shfl reduce all 4 accumulators
            float r0 = acc[0] + __shfl_xor_sync(0xffffffffu, acc[0], 16);
            float r1 = acc[1] + __shfl_xor_sync(0xffffffffu, acc[1], 16);
            float r2 = acc[2] + __shfl_xor_sync(0xffffffffu, acc[2], 16);
            float r3 = acc[3] + __shfl_xor_sync(0xffffffffu, acc[3], 16);
            float m01 = (lane & 16) ? r1 : r0;
            float m23 = (lane & 16) ? r3 : r2;
            m01 += __shfl_xor_sync(0xffffffffu, m01, 8);
            m23 += __shfl_xor_sync(0xffffffffu, m23, 8);
            float qv = (lane & 8) ? m23 : m01;
            qv += __shfl_xor_sync(0xffffffffu, qv, 4);
            qv += __shfl_xor_sync(0xffffffffu, qv, 2);
            qv += __shfl_xor_sync(0xffffffffu, qv, 1);
            // lane 0->t0, 16->t1, 8->t2, 24->t3
            if ((lane & 7) == 0) {
                int t = ((lane >> 4) & 1) + (((lane >> 3) & 1) << 1);
                lg[q][t][sg * 64 + si] = qv;
            }
            c0 = c1; c1 = cn;
        }
    }
    __syncthreads();

    // ---- softmax: warps 0..3, row t = wid ----
    if (wid < T_TILE) {
        const float vb = v_b[0];
        const int t = wid;
        float e[8];
        float m = -1e30f;
#pragma unroll
        for (int k = 0; k < 8; ++k) {
            int i = k * 32 + lane;
            e[k] = lg[0][t][i] + lg[1][t][i] + lg[2][t][i] + lg[3][t][i] + vb;
            m = fmaxf(m, e[k]);
        }
#pragma unroll
        for (int o = 16; o; o >>= 1) m = fmaxf(m, __shfl_xor_sync(0xffffffffu, m, o));
        float ssum = 0.f;
#pragma unroll
        for (int k = 0; k < 8; ++k) {
            e[k] = __expf(e[k] - m);
            ssum += e[k];
        }
#pragma unroll
        for (int o = 16; o; o >>= 1) ssum += __shfl_xor_sync(0xffffffffu, ssum, o);
        const float inv = 1.0f / ssum;
        float* oa = out_attn + ((size_t)b * T_DIM + t0 + t) * S_DIM;
#pragma unroll
        for (int k = 0; k < 8; ++k)
            oa[k * 32 + lane] = e[k] * inv;
    }
}

// ---------------------------------------------------------------------------
// Kernel 3: weighted = attn @ values. grid=(B, 2, T/16)=128 blocks, 256 thr.
// ---------------------------------------------------------------------------
__global__ __launch_bounds__(256) void av_kernel(
    const float* __restrict__ values,    // (B,S,D)
    const float* __restrict__ attn,      // (B*T, S) normalized
    float* __restrict__ out_w)           // (T,B,D)
{
    __shared__ float p_s[T_AV][S_DIM];   // 16 KB

    const int b   = blockIdx.x;
    const int dh  = blockIdx.y;
    const int t0  = blockIdx.z * T_AV;
    const int tid = threadIdx.x;

    {
        const float4* ap = (const float4*)(attn + ((size_t)b * T_DIM + t0) * S_DIM);
        float4* ps4 = (float4*)p_s;
        for (int i = tid; i < T_AV * S_DIM / 4; i += 256) ps4[i] = ap[i];
    }
    __syncthreads();

    const int d = dh * 256 + tid;
    const float* vp = values + (size_t)b * S_DIM * D_DIM + d;

    float w[T_AV];
#pragma unroll
    for (int t = 0; t < T_AV; ++t) w[t] = 0.f;

    float v0 = vp[0 * D_DIM];
    float v1 = vp[1 * D_DIM];
    float v2 = vp[2 * D_DIM];
    float v3 = vp[3 * D_DIM];

    for (int s = 0; s < S_DIM; s += 4) {
        float n0, n1, n2, n3;
        if (s + 4 < S_DIM) {
            n0 = vp[(size_t)(s + 4) * D_DIM];
            n1 = vp[(size_t)(s + 5) * D_DIM];
            n2 = vp[(size_t)(s + 6) * D_DIM];
            n3 = vp[(size_t)(s + 7) * D_DIM];
        }
#pragma unroll
        for (int t = 0; t < T_AV; ++t) {
            float4 p = *(const float4*)&p_s[t][s];
            w[t] += p.x * v0 + p.y * v1 + p.z * v2 + p.w * v3;
        }
        v0 = n0; v1 = n1; v2 = n2; v3 = n3;
    }

#pragma unroll
    for (int t = 0; t < T_AV; ++t)
        out_w[((size_t)(t0 + t) * B_DIM + b) * D_DIM + d] = w[t];
}

// ---------------------------------------------------------------------------
extern "C" void kernel_launch(void* const* d_in, const int* in_sizes, int n_in,
                              void* d_out, int out_size) {
    const float* input   = (const float*)d_in[0];
    const float* context = (const float*)d_in[1];
    const float* values  = (const float*)d_in[2];
    const float* W_comb  = (const float*)d_in[3];
    const float* b_comb  = (const float*)d_in[4];
    const float* v_w     = (const float*)d_in[5];
    const float* v_b     = (const float*)d_in[6];

    float* out_weighted = (float*)d_out;                                 // (T,B,D)
    float* out_attn     = (float*)d_out + (size_t)T_DIM * B_DIM * D_DIM; // (B*T,S)

    dim3 g1(D_DIM / 64, (T_DIM * B_DIM) / 64);           // (8,16)
    gemm_kernel<<<g1, 256>>>(input, W_comb, b_comb);

    dim3 g2(B_DIM, T_DIM / T_TILE);                      // (16,16) = 256 blocks
    logits_kernel<<<g2, 512>>>(context, v_w, v_b, out_attn);

    dim3 g3(B_DIM, 2, T_DIM / T_AV);                     // (16,2,4) = 128 blocks
    av_kernel<<<g3, 256>>>(values, out_attn, out_weighted);
}